// round 2
// baseline (speedup 1.0000x reference)
#include <cuda_runtime.h>
#include <cuda_bf16.h>
#include <float.h>
#include <limits.h>

// VectorQuantizerEMA forward (eval mode).
//   d_in[0] = X [65536, 256] f32,  d_in[1] = E [1024, 256] f32
//   out (f32): [quantized_st 16777216 | loss 1 | indices 65536]
//
// Phase 1: fp32 SIMT distance GEMM, per-row TOP-2 candidates.
// Phase 2: fp64 exact rescore of the 2 candidates -> exact argmin.

#define NROWS   65536
#define DDIM    256
#define KCODES  1024
#define M_TILE  128
#define N_CHUNK 64
#define NCHUNKS (KCODES / N_CHUNK)   // 16
#define THREADS 256
#define PAD     260                  // 256 + 4 floats: breaks smem bank conflicts

__device__ double g_loss_accum;
__device__ float  g_e2[KCODES];

// ---------------------------------------------------------------------------
__global__ void vq_prep(const float* __restrict__ E) {
    int c = blockIdx.x * blockDim.x + threadIdx.x;
    if (c == 0) g_loss_accum = 0.0;
    if (c < KCODES) {
        const float4* e4 = reinterpret_cast<const float4*>(E + (size_t)c * DDIM);
        float s = 0.0f;
#pragma unroll 8
        for (int i = 0; i < DDIM / 4; ++i) {
            float4 v = e4[i];
            s += v.x * v.x + v.y * v.y + v.z * v.z + v.w * v.w;
        }
        g_e2[c] = s;
    }
}

// insert candidate (d, c) into sorted top-2 (v1,i1)<(v2,i2); ties -> lower idx
__device__ __forceinline__ void top2_insert(float d, int c,
                                            float& v1, int& i1,
                                            float& v2, int& i2) {
    if (d < v1 || (d == v1 && c < i1)) {
        v2 = v1; i2 = i1; v1 = d; i1 = c;
    } else if (d < v2 || (d == v2 && c < i2)) {
        v2 = d; i2 = c;
    }
}

// ---------------------------------------------------------------------------
__global__ __launch_bounds__(THREADS, 1)
void vq_main(const float* __restrict__ X, const float* __restrict__ E,
             float* __restrict__ outQ, float* __restrict__ outIdx) {
    extern __shared__ float smem[];
    float* sX = smem;                        // M_TILE * PAD
    float* sE = smem + M_TILE * PAD;         // N_CHUNK * PAD
    __shared__ float sE2[KCODES];
    __shared__ float sBestVal[M_TILE];
    __shared__ int   sBestIdx[M_TILE];
    __shared__ float sSecVal[M_TILE];
    __shared__ int   sSecIdx[M_TILE];
    __shared__ float sRed[THREADS / 32];

    const int t       = threadIdx.x;
    const int rowbase = blockIdx.x * M_TILE;

    for (int i = t; i < KCODES; i += THREADS) sE2[i] = g_e2[i];
    if (t < M_TILE) {
        sBestVal[t] = FLT_MAX; sBestIdx[t] = INT_MAX;
        sSecVal[t]  = FLT_MAX; sSecIdx[t]  = INT_MAX;
    }

    // load X tile (128 x 256 f32) into padded smem
    {
        const float4* g = reinterpret_cast<const float4*>(X + (size_t)rowbase * DDIM);
        for (int i = t; i < M_TILE * (DDIM / 4); i += THREADS) {
            int r = i >> 6, c4 = i & 63;
            float4 v = g[(size_t)r * (DDIM / 4) + c4];
            *reinterpret_cast<float4*>(&sX[r * PAD + c4 * 4]) = v;
        }
    }
    __syncthreads();

    const int tr = t >> 4;   // 0..15, owns rows tr*8..tr*8+7
    const int tc = t & 15;   // 0..15, owns 4 codes per chunk

    for (int kc = 0; kc < NCHUNKS; ++kc) {
        {
            const float4* g = reinterpret_cast<const float4*>(
                E + (size_t)kc * N_CHUNK * DDIM);
            for (int i = t; i < N_CHUNK * (DDIM / 4); i += THREADS) {
                int r = i >> 6, c4 = i & 63;
                float4 v = g[(size_t)r * (DDIM / 4) + c4];
                *reinterpret_cast<float4*>(&sE[r * PAD + c4 * 4]) = v;
            }
        }
        __syncthreads();

        // 8x4 micro-tile fp32 dot products over D=256
        float acc[8][4];
#pragma unroll
        for (int i = 0; i < 8; ++i)
#pragma unroll
            for (int j = 0; j < 4; ++j) acc[i][j] = 0.0f;

        const float* xb = &sX[(tr * 8) * PAD];
        const float* eb = &sE[(tc * 4) * PAD];
#pragma unroll 2
        for (int d4 = 0; d4 < DDIM / 4; ++d4) {
            float4 ev[4];
#pragma unroll
            for (int j = 0; j < 4; ++j)
                ev[j] = *reinterpret_cast<const float4*>(&eb[j * PAD + d4 * 4]);
#pragma unroll
            for (int i = 0; i < 8; ++i) {
                float4 xv = *reinterpret_cast<const float4*>(&xb[i * PAD + d4 * 4]);
#pragma unroll
                for (int j = 0; j < 4; ++j) {
                    acc[i][j] += xv.x * ev[j].x + xv.y * ev[j].y +
                                 xv.z * ev[j].z + xv.w * ev[j].w;
                }
            }
        }

        // per-row TOP-2 over this chunk, then merge into running top-2
#pragma unroll
        for (int i = 0; i < 8; ++i) {
            float v1 = FLT_MAX, v2 = FLT_MAX;
            int   i1 = INT_MAX, i2 = INT_MAX;
#pragma unroll
            for (int j = 0; j < 4; ++j) {
                int   code = kc * N_CHUNK + tc * 4 + j;
                float dist = sE2[code] - 2.0f * acc[i][j];
                top2_insert(dist, code, v1, i1, v2, i2);
            }
            // reduce top-2 across the 16 tc-lanes (xor<16 stays in-group)
#pragma unroll
            for (int s = 8; s >= 1; s >>= 1) {
                float ov1 = __shfl_xor_sync(0xffffffffu, v1, s);
                int   oi1 = __shfl_xor_sync(0xffffffffu, i1, s);
                float ov2 = __shfl_xor_sync(0xffffffffu, v2, s);
                int   oi2 = __shfl_xor_sync(0xffffffffu, i2, s);
                top2_insert(ov1, oi1, v1, i1, v2, i2);
                top2_insert(ov2, oi2, v1, i1, v2, i2);
            }
            if (tc == 0) {
                int r = tr * 8 + i;   // unique writer for row r
                float rv1 = sBestVal[r], rv2 = sSecVal[r];
                int   ri1 = sBestIdx[r], ri2 = sSecIdx[r];
                top2_insert(v1, i1, rv1, ri1, rv2, ri2);
                top2_insert(v2, i2, rv1, ri1, rv2, ri2);
                sBestVal[r] = rv1; sBestIdx[r] = ri1;
                sSecVal[r]  = rv2; sSecIdx[r]  = ri2;
            }
        }
        __syncthreads();
    }

    // ---- Phase 2: exact fp64 rescore of the 2 candidates per row ----------
    // 256 threads = 128 rows x 2 candidates. Thread t -> row t>>1, cand t&1.
    {
        int r    = t >> 1;
        int cand = (t & 1) ? sSecIdx[r] : sBestIdx[r];
        const float4* e4 = reinterpret_cast<const float4*>(E + (size_t)cand * DDIM);
        const float*  xr = &sX[r * PAD];
        double a0 = 0.0, a1 = 0.0, a2 = 0.0, a3 = 0.0;
#pragma unroll 4
        for (int d4 = 0; d4 < DDIM / 4; ++d4) {
            float4 e = e4[d4];
            float4 x = *reinterpret_cast<const float4*>(&xr[d4 * 4]);
            double dx = (double)x.x - (double)e.x; a0 += dx * dx;
            double dy = (double)x.y - (double)e.y; a1 += dy * dy;
            double dz = (double)x.z - (double)e.z; a2 += dz * dz;
            double dw = (double)x.w - (double)e.w; a3 += dw * dw;
        }
        double dist = (a0 + a1) + (a2 + a3);
        double od   = __shfl_xor_sync(0xffffffffu, dist, 1);
        int   ocand = __shfl_xor_sync(0xffffffffu, cand, 1);
        int win = (dist < od || (dist == od && cand < ocand)) ? cand : ocand;
        if ((t & 1) == 0) sBestIdx[r] = win;
    }
    __syncthreads();

    // ---- epilogue: gather, straight-through output, loss partial ----------
    float lsum = 0.0f;
    for (int i = t; i < M_TILE * (DDIM / 4); i += THREADS) {
        int r = i >> 6, c4 = i & 63;
        int idx = sBestIdx[r];
        float4 e = *reinterpret_cast<const float4*>(E + (size_t)idx * DDIM + c4 * 4);
        float4 x = *reinterpret_cast<const float4*>(&sX[r * PAD + c4 * 4]);
        float4 d, q;
        d.x = e.x - x.x; d.y = e.y - x.y; d.z = e.z - x.z; d.w = e.w - x.w;
        q.x = x.x + d.x; q.y = x.y + d.y; q.z = x.z + d.z; q.w = x.w + d.w;
        lsum += d.x * d.x + d.y * d.y + d.z * d.z + d.w * d.w;
        *reinterpret_cast<float4*>(outQ + (size_t)(rowbase + r) * DDIM + c4 * 4) = q;
    }
    if (t < M_TILE) outIdx[rowbase + t] = (float)sBestIdx[t];

    // block-reduce loss partial, one double atomic per CTA
#pragma unroll
    for (int s = 16; s >= 1; s >>= 1)
        lsum += __shfl_xor_sync(0xffffffffu, lsum, s);
    if ((t & 31) == 0) sRed[t >> 5] = lsum;
    __syncthreads();
    if (t == 0) {
        float s = 0.0f;
        for (int w = 0; w < THREADS / 32; ++w) s += sRed[w];
        atomicAdd(&g_loss_accum, (double)s);
    }
}

// ---------------------------------------------------------------------------
__global__ void vq_finalize(float* __restrict__ outLoss) {
    if (threadIdx.x == 0)
        *outLoss = (float)(g_loss_accum * (1.0 / (double)((size_t)NROWS * DDIM)));
}

// ---------------------------------------------------------------------------
extern "C" void kernel_launch(void* const* d_in, const int* in_sizes, int n_in,
                              void* d_out, int out_size) {
    (void)in_sizes; (void)n_in; (void)out_size;
    const float* X = (const float*)d_in[0];
    const float* E = (const float*)d_in[1];

    float* outQ    = (float*)d_out;
    float* outLoss = outQ + (size_t)NROWS * DDIM;   // 16777216
    float* outIdx  = outLoss + 1;                   // 16777217

    const size_t smem_bytes = (size_t)(M_TILE + N_CHUNK) * PAD * sizeof(float);
    cudaFuncSetAttribute(vq_main, cudaFuncAttributeMaxDynamicSharedMemorySize,
                         (int)smem_bytes);

    vq_prep<<<(KCODES + 255) / 256, 256>>>(E);
    vq_main<<<NROWS / M_TILE, THREADS, smem_bytes>>>(X, E, outQ, outIdx);
    vq_finalize<<<1, 32>>>(outLoss);
}

// round 5
// speedup vs baseline: 2.3036x; 2.3036x over previous
#include <cuda_runtime.h>
#include <cuda_bf16.h>
#include <float.h>
#include <limits.h>
#include <stdint.h>

// VectorQuantizerEMA forward (eval mode).
//   d_in[0] = X [65536, 256] f32,  d_in[1] = E [1024, 256] f32
//   out (f32): [quantized_st 16777216 | loss 1 | indices 65536]
//
// Phase 1: bf16 hi/lo split scoring GEMM on mma.sync m16n8k16 (3 passes:
//          Xhi*Ehi + Xhi*Elo + Xlo*Ehi, fp32 accum; proxy sigma ~2e-4),
//          ||e||^2 folded into 2 augmented K-columns (4-term bf16 cascade),
//          per-row top-4 candidates. E chunks double-buffered via cp.async.
// Phase 2: exact fp64 rescore, diff form (validated bit-exact in R2).
// Epilogue: identical fp32 math to the reference.
//
// NOTE: harness compiles at compute_103 (no 'a'): tcgen05/TMEM unavailable;
// mma.sync + ldmatrix + cp.async are baseline PTX and work.

#define NROWS    65536
#define DDIM     256
#define KAUG     272               // 256 + 16 (cols 256/257 carry -|e|^2/2 cascade)
#define KSTEPS   (KAUG / 16)       // 17
#define KCODES   1024
#define M_TILE   128
#define THREADS  256
#define WARPS    8
#define CCHUNK   32                // codes per smem chunk
#define NCHUNKS  (KCODES / CCHUNK) // 32
#define NTILES   (CCHUNK / 8)      // 4
#define ESTRIDE  560               // bytes/row: 280 bf16 (272 used + pad)
#define XH_BYTES (M_TILE * ESTRIDE)       // 71680 (hi); lo same size
#define ECH      (CCHUNK * ESTRIDE)       // 17920 per (hi|lo) chunk
#define EBUF     (2 * ECH)                // 35840 per double-buffer slot
#define OFF_XHI  0
#define OFF_XLO  XH_BYTES
#define OFF_E    (2 * XH_BYTES)           // 143360
#define DYN_SMEM (OFF_E + 2 * EBUF)       // 215040

__device__ double g_loss_accum;
__device__ __align__(16) unsigned char g_Ehi[KCODES * ESTRIDE];
__device__ __align__(16) unsigned char g_Elo[KCODES * ESTRIDE];

// ---------------------------------------------------------------------------
__device__ __forceinline__ uint32_t smem_u32(const void* p) {
    uint32_t a;
    asm("{ .reg .u64 t; cvta.to.shared.u64 t, %1; cvt.u32.u64 %0, t; }"
        : "=r"(a) : "l"(p));
    return a;
}
__device__ __forceinline__ void ldmatrix_x4(uint32_t& r0, uint32_t& r1,
                                            uint32_t& r2, uint32_t& r3,
                                            uint32_t addr) {
    asm volatile("ldmatrix.sync.aligned.m8n8.x4.shared.b16 {%0,%1,%2,%3}, [%4];"
                 : "=r"(r0), "=r"(r1), "=r"(r2), "=r"(r3) : "r"(addr));
}
__device__ __forceinline__ void ldmatrix_x2(uint32_t& r0, uint32_t& r1,
                                            uint32_t addr) {
    asm volatile("ldmatrix.sync.aligned.m8n8.x2.shared.b16 {%0,%1}, [%2];"
                 : "=r"(r0), "=r"(r1) : "r"(addr));
}
__device__ __forceinline__ void mma_bf16(float& c0, float& c1, float& c2, float& c3,
                                         uint32_t a0, uint32_t a1, uint32_t a2,
                                         uint32_t a3, uint32_t b0, uint32_t b1) {
    asm volatile(
        "mma.sync.aligned.m16n8k16.row.col.f32.bf16.bf16.f32 "
        "{%0,%1,%2,%3}, {%4,%5,%6,%7}, {%8,%9}, {%0,%1,%2,%3};"
        : "+f"(c0), "+f"(c1), "+f"(c2), "+f"(c3)
        : "r"(a0), "r"(a1), "r"(a2), "r"(a3), "r"(b0), "r"(b1));
}
#define CP16(dst, src) \
    asm volatile("cp.async.cg.shared.global [%0], [%1], 16;" \
                 :: "r"(dst), "l"(src) : "memory")
#define CP_COMMIT() asm volatile("cp.async.commit_group;" ::: "memory")
#define CP_WAIT(n)  asm volatile("cp.async.wait_group %0;" :: "n"(n) : "memory")

// sorted top-4 by score desc; scan variant (strict '>', codes ascend in-lane)
__device__ __forceinline__ void ins4(float s, int c, float v[4], int ix[4]) {
    if (s > v[3]) {
        if (s > v[2]) {
            v[3] = v[2]; ix[3] = ix[2];
            if (s > v[1]) {
                v[2] = v[1]; ix[2] = ix[1];
                if (s > v[0]) { v[1] = v[0]; ix[1] = ix[0]; v[0] = s; ix[0] = c; }
                else          { v[1] = s; ix[1] = c; }
            } else { v[2] = s; ix[2] = c; }
        } else { v[3] = s; ix[3] = c; }
    }
}
// merge variant: tie -> lower code index
__device__ __forceinline__ void ins4tb(float s, int c, float v[4], int ix[4]) {
    if (s > v[3] || (s == v[3] && c < ix[3])) {
        if (s > v[2] || (s == v[2] && c < ix[2])) {
            v[3] = v[2]; ix[3] = ix[2];
            if (s > v[1] || (s == v[1] && c < ix[1])) {
                v[2] = v[1]; ix[2] = ix[1];
                if (s > v[0] || (s == v[0] && c < ix[0])) {
                    v[1] = v[0]; ix[1] = ix[0]; v[0] = s; ix[0] = c;
                } else { v[1] = s; ix[1] = c; }
            } else { v[2] = s; ix[2] = c; }
        } else { v[3] = s; ix[3] = c; }
    }
}

// ---------------------------------------------------------------------------
// prep: E -> bf16 hi/lo rows of 280 (272 used); aug cols 256/257 carry a
// 4-term bf16 cascade of -|e|^2/2 split across (hi,lo) planes.
// grid = 128 blocks x 256 threads; one warp per code.
// ---------------------------------------------------------------------------
__global__ void vq_prep(const float* __restrict__ E) {
    const int w = threadIdx.x >> 5, lane = threadIdx.x & 31;
    const int code = blockIdx.x * 8 + w;
    if (blockIdx.x == 0 && threadIdx.x == 0) g_loss_accum = 0.0;

    const float4* e4 = reinterpret_cast<const float4*>(E + (size_t)code * DDIM);
    float4 va = e4[lane * 2], vb = e4[lane * 2 + 1];

    float f[8] = {va.x, va.y, va.z, va.w, vb.x, vb.y, vb.z, vb.w};
    uint32_t hi[4], lo[4];
    double s = 0.0;
#pragma unroll
    for (int j = 0; j < 4; ++j) {
        float x0 = f[j * 2], x1 = f[j * 2 + 1];
        __nv_bfloat16 h0 = __float2bfloat16_rn(x0);
        __nv_bfloat16 h1 = __float2bfloat16_rn(x1);
        __nv_bfloat162 hp = __halves2bfloat162(h0, h1);
        __nv_bfloat162 lp = __floats2bfloat162_rn(x0 - __bfloat162float(h0),
                                                  x1 - __bfloat162float(h1));
        hi[j] = *reinterpret_cast<uint32_t*>(&hp);
        lo[j] = *reinterpret_cast<uint32_t*>(&lp);
        s += (double)x0 * x0 + (double)x1 * x1;
    }
    *reinterpret_cast<uint4*>(g_Ehi + (size_t)code * ESTRIDE + lane * 16) =
        make_uint4(hi[0], hi[1], hi[2], hi[3]);
    *reinterpret_cast<uint4*>(g_Elo + (size_t)code * ESTRIDE + lane * 16) =
        make_uint4(lo[0], lo[1], lo[2], lo[3]);

#pragma unroll
    for (int o = 16; o >= 1; o >>= 1)
        s += __shfl_xor_sync(0xffffffffu, s, o);

    if (lane == 0) {
        // cascade -|e|^2/2 = h1 + h2 + h3 + h4 (+ ~1e-6 residual)
        double d = -0.5 * s;
        __nv_bfloat16 h1 = __float2bfloat16_rn((float)d);
        d -= (double)__bfloat162float(h1);
        __nv_bfloat16 h2 = __float2bfloat16_rn((float)d);
        d -= (double)__bfloat162float(h2);
        __nv_bfloat16 h3 = __float2bfloat16_rn((float)d);
        d -= (double)__bfloat162float(h3);
        __nv_bfloat16 h4 = __float2bfloat16_rn((float)d);
        // X aug cols 256,257 are 1.0 in Xhi, 0 in Xlo. Contributions summed:
        //   Ehi[256]+Ehi[257] (pass Xhi*Ehi) + Elo[256]+Elo[257] (pass Xhi*Elo)
        uint32_t whi = (uint32_t)*reinterpret_cast<unsigned short*>(&h1) |
                       ((uint32_t)*reinterpret_cast<unsigned short*>(&h3) << 16);
        uint32_t wlo = (uint32_t)*reinterpret_cast<unsigned short*>(&h2) |
                       ((uint32_t)*reinterpret_cast<unsigned short*>(&h4) << 16);
        unsigned char* bh = g_Ehi + (size_t)code * ESTRIDE + 512;
        unsigned char* bl = g_Elo + (size_t)code * ESTRIDE + 512;
        *reinterpret_cast<uint4*>(bh +  0) = make_uint4(whi, 0u, 0u, 0u);
        *reinterpret_cast<uint4*>(bh + 16) = make_uint4(0u, 0u, 0u, 0u);
        *reinterpret_cast<uint4*>(bh + 32) = make_uint4(0u, 0u, 0u, 0u);
        *reinterpret_cast<uint4*>(bl +  0) = make_uint4(wlo, 0u, 0u, 0u);
        *reinterpret_cast<uint4*>(bl + 16) = make_uint4(0u, 0u, 0u, 0u);
        *reinterpret_cast<uint4*>(bl + 32) = make_uint4(0u, 0u, 0u, 0u);
    }
}

// ---------------------------------------------------------------------------
__device__ __forceinline__ void prefetch_chunk(uint32_t dst, int chunk, int tid) {
    const unsigned char* sh = g_Ehi + (size_t)chunk * ECH;
    const unsigned char* sl = g_Elo + (size_t)chunk * ECH;
#pragma unroll 1
    for (int i = tid; i < ECH / 16; i += THREADS) {
        CP16(dst + (uint32_t)i * 16u,        sh + (size_t)i * 16);
        CP16(dst + ECH + (uint32_t)i * 16u,  sl + (size_t)i * 16);
    }
    CP_COMMIT();
}

// ---------------------------------------------------------------------------
// main: 512 CTAs x 256 threads (8 warps); warp w owns rows w*16 .. w*16+15.
// ---------------------------------------------------------------------------
__global__ __launch_bounds__(THREADS, 1)
void vq_main_mma(const float* __restrict__ X, const float* __restrict__ E,
                 float* __restrict__ outQ, float* __restrict__ outIdx) {
    extern __shared__ __align__(16) unsigned char sm[];
    __shared__ int   sCand[M_TILE][4];
    __shared__ int   sWin[M_TILE];
    __shared__ float sRed[WARPS];

    const int tid  = threadIdx.x;
    const int w    = tid >> 5;
    const int lane = tid & 31;
    const int rowbase = blockIdx.x * M_TILE;

    const uint32_t sm_u = smem_u32(sm);
    const uint32_t Eu   = sm_u + OFF_E;

    // kick off E chunk 0 prefetch immediately (region disjoint from X staging)
    prefetch_chunk(Eu, 0, tid);

    // ---- stage X tile: f32 -> bf16 hi/lo rows of 280 + aug cols -----------
    for (int i = tid; i < M_TILE * 3; i += THREADS) {
        int r = i / 3, part = i % 3;
        uint4 zero = make_uint4(0u, 0u, 0u, 0u);
        uint4 vhi  = (part == 0) ? make_uint4(0x3F803F80u, 0u, 0u, 0u) : zero;
        *reinterpret_cast<uint4*>(sm + OFF_XHI + r * ESTRIDE + 512 + part * 16) = vhi;
        *reinterpret_cast<uint4*>(sm + OFF_XLO + r * ESTRIDE + 512 + part * 16) = zero;
    }
    {
        const float4* xg = reinterpret_cast<const float4*>(X + (size_t)rowbase * DDIM);
        for (int i = tid; i < M_TILE * (DDIM / 4); i += THREADS) {
            int r = i >> 6, c4 = i & 63;
            float4 v = xg[i];
            __nv_bfloat16 h0 = __float2bfloat16_rn(v.x);
            __nv_bfloat16 h1 = __float2bfloat16_rn(v.y);
            __nv_bfloat16 h2 = __float2bfloat16_rn(v.z);
            __nv_bfloat16 h3 = __float2bfloat16_rn(v.w);
            __nv_bfloat162 hp0 = __halves2bfloat162(h0, h1);
            __nv_bfloat162 hp1 = __halves2bfloat162(h2, h3);
            __nv_bfloat162 lp0 = __floats2bfloat162_rn(v.x - __bfloat162float(h0),
                                                       v.y - __bfloat162float(h1));
            __nv_bfloat162 lp1 = __floats2bfloat162_rn(v.z - __bfloat162float(h2),
                                                       v.w - __bfloat162float(h3));
            uint2 oh, ol;
            oh.x = *reinterpret_cast<uint32_t*>(&hp0);
            oh.y = *reinterpret_cast<uint32_t*>(&hp1);
            ol.x = *reinterpret_cast<uint32_t*>(&lp0);
            ol.y = *reinterpret_cast<uint32_t*>(&lp1);
            *reinterpret_cast<uint2*>(sm + OFF_XHI + r * ESTRIDE + c4 * 8) = oh;
            *reinterpret_cast<uint2*>(sm + OFF_XLO + r * ESTRIDE + c4 * 8) = ol;
        }
    }
    __syncthreads();

    // ---- register-resident A fragments, hi and lo (17 x 4 regs each) ------
    uint32_t ah[KSTEPS][4], al[KSTEPS][4];
    {
        uint32_t off = (uint32_t)(w * 16 + (lane & 15)) * ESTRIDE +
                       (uint32_t)((lane >> 4) * 16);
#pragma unroll
        for (int s = 0; s < KSTEPS; ++s) {
            ldmatrix_x4(ah[s][0], ah[s][1], ah[s][2], ah[s][3],
                        sm_u + OFF_XHI + off + s * 32);
            ldmatrix_x4(al[s][0], al[s][1], al[s][2], al[s][3],
                        sm_u + OFF_XLO + off + s * 32);
        }
    }

    // ---- score all codes; per-thread running top-4 for rows (A, A+8) ------
    float vA[4] = {-FLT_MAX, -FLT_MAX, -FLT_MAX, -FLT_MAX};
    float vB[4] = {-FLT_MAX, -FLT_MAX, -FLT_MAX, -FLT_MAX};
    int ixA[4] = {INT_MAX, INT_MAX, INT_MAX, INT_MAX};
    int ixB[4] = {INT_MAX, INT_MAX, INT_MAX, INT_MAX};

    const uint32_t brow = (uint32_t)(lane & 7) * ESTRIDE +
                          (uint32_t)(((lane >> 3) & 1) * 16);

    for (int chunk = 0; chunk < NCHUNKS; ++chunk) {
        const uint32_t buf = Eu + (uint32_t)(chunk & 1) * EBUF;
        if (chunk + 1 < NCHUNKS) {
            prefetch_chunk(Eu + (uint32_t)((chunk + 1) & 1) * EBUF, chunk + 1, tid);
            CP_WAIT(1);               // current buffer complete
        } else {
            CP_WAIT(0);
        }
        __syncthreads();

#pragma unroll
        for (int nt = 0; nt < NTILES; ++nt) {
            float c0 = 0.f, c1 = 0.f, c2 = 0.f, c3 = 0.f;
            uint32_t bh = buf + brow + (uint32_t)(nt * 8) * ESTRIDE;
            uint32_t bl = bh + ECH;
#pragma unroll
            for (int s = 0; s < KSTEPS; ++s) {
                uint32_t bh0, bh1, bl0, bl1;
                ldmatrix_x2(bh0, bh1, bh + s * 32);
                ldmatrix_x2(bl0, bl1, bl + s * 32);
                mma_bf16(c0, c1, c2, c3, ah[s][0], ah[s][1], ah[s][2], ah[s][3], bh0, bh1);
                mma_bf16(c0, c1, c2, c3, ah[s][0], ah[s][1], ah[s][2], ah[s][3], bl0, bl1);
                mma_bf16(c0, c1, c2, c3, al[s][0], al[s][1], al[s][2], al[s][3], bh0, bh1);
            }
            int code = chunk * CCHUNK + nt * 8 + (lane & 3) * 2;
            ins4(c0, code,     vA, ixA);
            ins4(c1, code + 1, vA, ixA);
            ins4(c2, code,     vB, ixB);
            ins4(c3, code + 1, vB, ixB);
        }
        __syncthreads();              // done reading buf before it is refilled
    }

    // ---- merge top-4 across the 4 lanes sharing each row ------------------
#pragma unroll
    for (int o = 1; o <= 2; o <<= 1) {
#pragma unroll
        for (int j = 0; j < 4; ++j) {
            float ovA = __shfl_xor_sync(0xffffffffu, vA[j], o);
            int   oiA = __shfl_xor_sync(0xffffffffu, ixA[j], o);
            float ovB = __shfl_xor_sync(0xffffffffu, vB[j], o);
            int   oiB = __shfl_xor_sync(0xffffffffu, ixB[j], o);
            ins4tb(ovA, oiA, vA, ixA);
            ins4tb(ovB, oiB, vB, ixB);
        }
    }
    if ((lane & 3) == 0) {
        int rA = w * 16 + (lane >> 2);
#pragma unroll
        for (int j = 0; j < 4; ++j) {
            sCand[rA][j]     = ixA[j];
            sCand[rA + 8][j] = ixB[j];
        }
    }
    __syncthreads();

    // ---- Phase 2: exact fp64 rescore, diff form (R2-validated) ------------
    {
        int r  = tid >> 1;
        int cA = sCand[r][(tid & 1) * 2];
        int cB = sCand[r][(tid & 1) * 2 + 1];
        const float4* x4 = reinterpret_cast<const float4*>(X + (size_t)(rowbase + r) * DDIM);
        const float4* ea = reinterpret_cast<const float4*>(E + (size_t)cA * DDIM);
        const float4* eb = reinterpret_cast<const float4*>(E + (size_t)cB * DDIM);
        double dA = 0.0, dB = 0.0;
#pragma unroll 4
        for (int j = 0; j < DDIM / 4; ++j) {
            float4 xv = x4[j], va = ea[j], vb = eb[j];
            double d;
            d = (double)xv.x - (double)va.x; dA += d * d;
            d = (double)xv.y - (double)va.y; dA += d * d;
            d = (double)xv.z - (double)va.z; dA += d * d;
            d = (double)xv.w - (double)va.w; dA += d * d;
            d = (double)xv.x - (double)vb.x; dB += d * d;
            d = (double)xv.y - (double)vb.y; dB += d * d;
            d = (double)xv.z - (double)vb.z; dB += d * d;
            d = (double)xv.w - (double)vb.w; dB += d * d;
        }
        double dmin = dA; int cmin = cA;
        if (dB < dmin || (dB == dmin && cB < cmin)) { dmin = dB; cmin = cB; }
        double od = __shfl_xor_sync(0xffffffffu, dmin, 1);
        int    oc = __shfl_xor_sync(0xffffffffu, cmin, 1);
        if (od < dmin || (od == dmin && oc < cmin)) { cmin = oc; }
        if ((tid & 1) == 0) sWin[r] = cmin;
    }
    __syncthreads();

    // ---- epilogue: gather + straight-through + loss (bit-exact to R2) -----
    float lsum = 0.0f;
    {
        const float4* xg = reinterpret_cast<const float4*>(X + (size_t)rowbase * DDIM);
        for (int i = tid; i < M_TILE * (DDIM / 4); i += THREADS) {
            int r = i >> 6, c4 = i & 63;
            int idx = sWin[r];
            float4 e = *reinterpret_cast<const float4*>(E + (size_t)idx * DDIM + c4 * 4);
            float4 x = xg[i];
            float4 d, q;
            d.x = e.x - x.x; d.y = e.y - x.y; d.z = e.z - x.z; d.w = e.w - x.w;
            q.x = x.x + d.x; q.y = x.y + d.y; q.z = x.z + d.z; q.w = x.w + d.w;
            lsum += d.x * d.x + d.y * d.y + d.z * d.z + d.w * d.w;
            *reinterpret_cast<float4*>(outQ + (size_t)(rowbase + r) * DDIM + c4 * 4) = q;
        }
    }
    if (tid < M_TILE) outIdx[rowbase + tid] = (float)sWin[tid];

#pragma unroll
    for (int s = 16; s >= 1; s >>= 1)
        lsum += __shfl_xor_sync(0xffffffffu, lsum, s);
    if (lane == 0) sRed[w] = lsum;
    __syncthreads();
    if (tid == 0) {
        float s = 0.0f;
#pragma unroll
        for (int i = 0; i < WARPS; ++i) s += sRed[i];
        atomicAdd(&g_loss_accum, (double)s);
    }
}

// ---------------------------------------------------------------------------
__global__ void vq_finalize(float* __restrict__ outLoss) {
    if (threadIdx.x == 0)
        *outLoss = (float)(g_loss_accum * (1.0 / (double)((size_t)NROWS * DDIM)));
}

// ---------------------------------------------------------------------------
extern "C" void kernel_launch(void* const* d_in, const int* in_sizes, int n_in,
                              void* d_out, int out_size) {
    (void)in_sizes; (void)n_in; (void)out_size;
    const float* X = (const float*)d_in[0];
    const float* E = (const float*)d_in[1];

    float* outQ    = (float*)d_out;
    float* outLoss = outQ + (size_t)NROWS * DDIM;   // 16777216
    float* outIdx  = outLoss + 1;                   // 16777217

    cudaFuncSetAttribute(vq_main_mma, cudaFuncAttributeMaxDynamicSharedMemorySize,
                         DYN_SMEM);

    vq_prep<<<KCODES / 8, 256>>>(E);
    vq_main_mma<<<NROWS / M_TILE, THREADS, DYN_SMEM>>>(X, E, outQ, outIdx);
    vq_finalize<<<1, 32>>>(outLoss);
}

// round 8
// speedup vs baseline: 2.4419x; 1.0600x over previous
#include <cuda_runtime.h>
#include <cuda_bf16.h>
#include <float.h>
#include <limits.h>
#include <stdint.h>

// VectorQuantizerEMA forward (eval mode).
//   d_in[0] = X [65536, 256] f32,  d_in[1] = E [1024, 256] f32
//   out (f32): [quantized_st 16777216 | loss 1 | indices 65536]
//
// Phase 1: bf16 hi/lo split scoring GEMM on mma.sync m16n8k16.
//   3 split passes use SEPARATE accumulators and 2 n-tiles are processed
//   concurrently -> 6 independent MMA dependency chains per warp
//   (was 1 serialized chain of 51). ||e||^2 folded via 2 augmented K-cols.
//   Per-row top-4 candidates; E chunks double-buffered via cp.async.
// Phase 2: exact fp64 rescore, diff form (validated bit-exact in R2/R5).
// Epilogue: identical fp32 math to the reference.
//
// NOTE: harness compiles at compute_103 (no 'a'): tcgen05/TMEM unavailable;
// mma.sync + ldmatrix + cp.async are baseline PTX and work.

#define NROWS    65536
#define DDIM     256
#define KAUG     272               // 256 + 16 (cols 256/257 carry -|e|^2/2 cascade)
#define KSTEPS   (KAUG / 16)       // 17
#define KCODES   1024
#define M_TILE   128
#define THREADS  256
#define WARPS    8
#define CCHUNK   32                // codes per smem chunk
#define NCHUNKS  (KCODES / CCHUNK) // 32
#define ESTRIDE  560               // bytes/row: 280 bf16 (272 used + pad)
#define XH_BYTES (M_TILE * ESTRIDE)       // 71680 (hi); lo same size
#define ECH      (CCHUNK * ESTRIDE)       // 17920 per (hi|lo) chunk
#define EBUF     (2 * ECH)                // 35840 per double-buffer slot
#define OFF_XHI  0
#define OFF_XLO  XH_BYTES
#define OFF_E    (2 * XH_BYTES)           // 143360
#define DYN_SMEM (OFF_E + 2 * EBUF)       // 215040

__device__ double g_loss_accum;
__device__ __align__(16) unsigned char g_Ehi[KCODES * ESTRIDE];
__device__ __align__(16) unsigned char g_Elo[KCODES * ESTRIDE];

// ---------------------------------------------------------------------------
__device__ __forceinline__ uint32_t smem_u32(const void* p) {
    uint32_t a;
    asm("{ .reg .u64 t; cvta.to.shared.u64 t, %1; cvt.u32.u64 %0, t; }"
        : "=r"(a) : "l"(p));
    return a;
}
__device__ __forceinline__ void ldmatrix_x4(uint32_t& r0, uint32_t& r1,
                                            uint32_t& r2, uint32_t& r3,
                                            uint32_t addr) {
    asm volatile("ldmatrix.sync.aligned.m8n8.x4.shared.b16 {%0,%1,%2,%3}, [%4];"
                 : "=r"(r0), "=r"(r1), "=r"(r2), "=r"(r3) : "r"(addr));
}
__device__ __forceinline__ void ldmatrix_x2(uint32_t& r0, uint32_t& r1,
                                            uint32_t addr) {
    asm volatile("ldmatrix.sync.aligned.m8n8.x2.shared.b16 {%0,%1}, [%2];"
                 : "=r"(r0), "=r"(r1) : "r"(addr));
}
__device__ __forceinline__ void mma4(float c[4], const uint32_t a[4],
                                     uint32_t b0, uint32_t b1) {
    asm volatile(
        "mma.sync.aligned.m16n8k16.row.col.f32.bf16.bf16.f32 "
        "{%0,%1,%2,%3}, {%4,%5,%6,%7}, {%8,%9}, {%0,%1,%2,%3};"
        : "+f"(c[0]), "+f"(c[1]), "+f"(c[2]), "+f"(c[3])
        : "r"(a[0]), "r"(a[1]), "r"(a[2]), "r"(a[3]), "r"(b0), "r"(b1));
}
#define CP16(dst, src) \
    asm volatile("cp.async.cg.shared.global [%0], [%1], 16;" \
                 :: "r"(dst), "l"(src) : "memory")
#define CP_COMMIT() asm volatile("cp.async.commit_group;" ::: "memory")
#define CP_WAIT(n)  asm volatile("cp.async.wait_group %0;" :: "n"(n) : "memory")

// sorted top-4 by score desc; scan variant (strict '>', codes ascend in-lane)
__device__ __forceinline__ void ins4(float s, int c, float v[4], int ix[4]) {
    if (s > v[3]) {
        if (s > v[2]) {
            v[3] = v[2]; ix[3] = ix[2];
            if (s > v[1]) {
                v[2] = v[1]; ix[2] = ix[1];
                if (s > v[0]) { v[1] = v[0]; ix[1] = ix[0]; v[0] = s; ix[0] = c; }
                else          { v[1] = s; ix[1] = c; }
            } else { v[2] = s; ix[2] = c; }
        } else { v[3] = s; ix[3] = c; }
    }
}
// merge variant: tie -> lower code index
__device__ __forceinline__ void ins4tb(float s, int c, float v[4], int ix[4]) {
    if (s > v[3] || (s == v[3] && c < ix[3])) {
        if (s > v[2] || (s == v[2] && c < ix[2])) {
            v[3] = v[2]; ix[3] = ix[2];
            if (s > v[1] || (s == v[1] && c < ix[1])) {
                v[2] = v[1]; ix[2] = ix[1];
                if (s > v[0] || (s == v[0] && c < ix[0])) {
                    v[1] = v[0]; ix[1] = ix[0]; v[0] = s; ix[0] = c;
                } else { v[1] = s; ix[1] = c; }
            } else { v[2] = s; ix[2] = c; }
        } else { v[3] = s; ix[3] = c; }
    }
}

// ---------------------------------------------------------------------------
// prep: E -> bf16 hi/lo rows of 280 (272 used); aug cols 256/257 carry a
// 4-term bf16 cascade of -|e|^2/2 split across (hi,lo) planes.
// ---------------------------------------------------------------------------
__global__ void vq_prep(const float* __restrict__ E) {
    const int w = threadIdx.x >> 5, lane = threadIdx.x & 31;
    const int code = blockIdx.x * 8 + w;
    if (blockIdx.x == 0 && threadIdx.x == 0) g_loss_accum = 0.0;

    const float4* e4 = reinterpret_cast<const float4*>(E + (size_t)code * DDIM);
    float4 va = e4[lane * 2], vb = e4[lane * 2 + 1];

    float f[8] = {va.x, va.y, va.z, va.w, vb.x, vb.y, vb.z, vb.w};
    uint32_t hi[4], lo[4];
    double s = 0.0;
#pragma unroll
    for (int j = 0; j < 4; ++j) {
        float x0 = f[j * 2], x1 = f[j * 2 + 1];
        __nv_bfloat16 h0 = __float2bfloat16_rn(x0);
        __nv_bfloat16 h1 = __float2bfloat16_rn(x1);
        __nv_bfloat162 hp = __halves2bfloat162(h0, h1);
        __nv_bfloat162 lp = __floats2bfloat162_rn(x0 - __bfloat162float(h0),
                                                  x1 - __bfloat162float(h1));
        hi[j] = *reinterpret_cast<uint32_t*>(&hp);
        lo[j] = *reinterpret_cast<uint32_t*>(&lp);
        s += (double)x0 * x0 + (double)x1 * x1;
    }
    *reinterpret_cast<uint4*>(g_Ehi + (size_t)code * ESTRIDE + lane * 16) =
        make_uint4(hi[0], hi[1], hi[2], hi[3]);
    *reinterpret_cast<uint4*>(g_Elo + (size_t)code * ESTRIDE + lane * 16) =
        make_uint4(lo[0], lo[1], lo[2], lo[3]);

#pragma unroll
    for (int o = 16; o >= 1; o >>= 1)
        s += __shfl_xor_sync(0xffffffffu, s, o);

    if (lane == 0) {
        double d = -0.5 * s;
        __nv_bfloat16 h1 = __float2bfloat16_rn((float)d);
        d -= (double)__bfloat162float(h1);
        __nv_bfloat16 h2 = __float2bfloat16_rn((float)d);
        d -= (double)__bfloat162float(h2);
        __nv_bfloat16 h3 = __float2bfloat16_rn((float)d);
        d -= (double)__bfloat162float(h3);
        __nv_bfloat16 h4 = __float2bfloat16_rn((float)d);
        uint32_t whi = (uint32_t)*reinterpret_cast<unsigned short*>(&h1) |
                       ((uint32_t)*reinterpret_cast<unsigned short*>(&h3) << 16);
        uint32_t wlo = (uint32_t)*reinterpret_cast<unsigned short*>(&h2) |
                       ((uint32_t)*reinterpret_cast<unsigned short*>(&h4) << 16);
        unsigned char* bh = g_Ehi + (size_t)code * ESTRIDE + 512;
        unsigned char* bl = g_Elo + (size_t)code * ESTRIDE + 512;
        *reinterpret_cast<uint4*>(bh +  0) = make_uint4(whi, 0u, 0u, 0u);
        *reinterpret_cast<uint4*>(bh + 16) = make_uint4(0u, 0u, 0u, 0u);
        *reinterpret_cast<uint4*>(bh + 32) = make_uint4(0u, 0u, 0u, 0u);
        *reinterpret_cast<uint4*>(bl +  0) = make_uint4(wlo, 0u, 0u, 0u);
        *reinterpret_cast<uint4*>(bl + 16) = make_uint4(0u, 0u, 0u, 0u);
        *reinterpret_cast<uint4*>(bl + 32) = make_uint4(0u, 0u, 0u, 0u);
    }
}

// ---------------------------------------------------------------------------
__device__ __forceinline__ void prefetch_chunk(uint32_t dst, int chunk, int tid) {
    const unsigned char* sh = g_Ehi + (size_t)chunk * ECH;
    const unsigned char* sl = g_Elo + (size_t)chunk * ECH;
#pragma unroll 1
    for (int i = tid; i < ECH / 16; i += THREADS) {
        CP16(dst + (uint32_t)i * 16u,        sh + (size_t)i * 16);
        CP16(dst + ECH + (uint32_t)i * 16u,  sl + (size_t)i * 16);
    }
    CP_COMMIT();
}

// ---------------------------------------------------------------------------
// main: 512 CTAs x 256 threads (8 warps); warp w owns rows w*16 .. w*16+15.
// ---------------------------------------------------------------------------
__global__ __launch_bounds__(THREADS, 1)
void vq_main_mma(const float* __restrict__ X, const float* __restrict__ E,
                 float* __restrict__ outQ, float* __restrict__ outIdx) {
    extern __shared__ __align__(16) unsigned char sm[];
    __shared__ int   sCand[M_TILE][4];
    __shared__ int   sWin[M_TILE];
    __shared__ float sRed[WARPS];

    const int tid  = threadIdx.x;
    const int w    = tid >> 5;
    const int lane = tid & 31;
    const int rowbase = blockIdx.x * M_TILE;

    const uint32_t sm_u = smem_u32(sm);
    const uint32_t Eu   = sm_u + OFF_E;

    // kick off E chunk 0 prefetch immediately (region disjoint from X staging)
    prefetch_chunk(Eu, 0, tid);

    // ---- stage X tile: f32 -> bf16 hi/lo rows of 280 + aug cols -----------
    for (int i = tid; i < M_TILE * 3; i += THREADS) {
        int r = i / 3, part = i % 3;
        uint4 zero = make_uint4(0u, 0u, 0u, 0u);
        uint4 vhi  = (part == 0) ? make_uint4(0x3F803F80u, 0u, 0u, 0u) : zero;
        *reinterpret_cast<uint4*>(sm + OFF_XHI + r * ESTRIDE + 512 + part * 16) = vhi;
        *reinterpret_cast<uint4*>(sm + OFF_XLO + r * ESTRIDE + 512 + part * 16) = zero;
    }
    {
        const float4* xg = reinterpret_cast<const float4*>(X + (size_t)rowbase * DDIM);
        for (int i = tid; i < M_TILE * (DDIM / 4); i += THREADS) {
            int r = i >> 6, c4 = i & 63;
            float4 v = xg[i];
            __nv_bfloat16 h0 = __float2bfloat16_rn(v.x);
            __nv_bfloat16 h1 = __float2bfloat16_rn(v.y);
            __nv_bfloat16 h2 = __float2bfloat16_rn(v.z);
            __nv_bfloat16 h3 = __float2bfloat16_rn(v.w);
            __nv_bfloat162 hp0 = __halves2bfloat162(h0, h1);
            __nv_bfloat162 hp1 = __halves2bfloat162(h2, h3);
            __nv_bfloat162 lp0 = __floats2bfloat162_rn(v.x - __bfloat162float(h0),
                                                       v.y - __bfloat162float(h1));
            __nv_bfloat162 lp1 = __floats2bfloat162_rn(v.z - __bfloat162float(h2),
                                                       v.w - __bfloat162float(h3));
            uint2 oh, ol;
            oh.x = *reinterpret_cast<uint32_t*>(&hp0);
            oh.y = *reinterpret_cast<uint32_t*>(&hp1);
            ol.x = *reinterpret_cast<uint32_t*>(&lp0);
            ol.y = *reinterpret_cast<uint32_t*>(&lp1);
            *reinterpret_cast<uint2*>(sm + OFF_XHI + r * ESTRIDE + c4 * 8) = oh;
            *reinterpret_cast<uint2*>(sm + OFF_XLO + r * ESTRIDE + c4 * 8) = ol;
        }
    }
    __syncthreads();

    // ---- register-resident A fragments, hi and lo (17 x 4 regs each) ------
    uint32_t ah[KSTEPS][4], al[KSTEPS][4];
    {
        uint32_t off = (uint32_t)(w * 16 + (lane & 15)) * ESTRIDE +
                       (uint32_t)((lane >> 4) * 16);
#pragma unroll
        for (int s = 0; s < KSTEPS; ++s) {
            ldmatrix_x4(ah[s][0], ah[s][1], ah[s][2], ah[s][3],
                        sm_u + OFF_XHI + off + s * 32);
            ldmatrix_x4(al[s][0], al[s][1], al[s][2], al[s][3],
                        sm_u + OFF_XLO + off + s * 32);
        }
    }

    // ---- score all codes; per-thread running top-4 for rows (A, A+8) ------
    float vA[4] = {-FLT_MAX, -FLT_MAX, -FLT_MAX, -FLT_MAX};
    float vB[4] = {-FLT_MAX, -FLT_MAX, -FLT_MAX, -FLT_MAX};
    int ixA[4] = {INT_MAX, INT_MAX, INT_MAX, INT_MAX};
    int ixB[4] = {INT_MAX, INT_MAX, INT_MAX, INT_MAX};

    const uint32_t brow = (uint32_t)(lane & 7) * ESTRIDE +
                          (uint32_t)(((lane >> 3) & 1) * 16);

    for (int chunk = 0; chunk < NCHUNKS; ++chunk) {
        const uint32_t buf = Eu + (uint32_t)(chunk & 1) * EBUF;
        if (chunk + 1 < NCHUNKS) {
            prefetch_chunk(Eu + (uint32_t)((chunk + 1) & 1) * EBUF, chunk + 1, tid);
            CP_WAIT(1);               // current buffer complete
        } else {
            CP_WAIT(0);
        }
        __syncthreads();

        // 2 n-tile pairs; per pair: 6 independent accumulator chains
#pragma unroll
        for (int ntp = 0; ntp < 2; ++ntp) {
            float hh0[4] = {0.f, 0.f, 0.f, 0.f}, hl0[4] = {0.f, 0.f, 0.f, 0.f};
            float lh0[4] = {0.f, 0.f, 0.f, 0.f};
            float hh1[4] = {0.f, 0.f, 0.f, 0.f}, hl1[4] = {0.f, 0.f, 0.f, 0.f};
            float lh1[4] = {0.f, 0.f, 0.f, 0.f};
            uint32_t b0h = buf + brow + (uint32_t)(ntp * 16) * ESTRIDE;
            uint32_t b1h = b0h + 8u * ESTRIDE;
            uint32_t b0l = b0h + ECH;
            uint32_t b1l = b1h + ECH;
#pragma unroll
            for (int s = 0; s < KSTEPS; ++s) {
                uint32_t q0h0, q0h1, q0l0, q0l1, q1h0, q1h1, q1l0, q1l1;
                ldmatrix_x2(q0h0, q0h1, b0h + s * 32);
                ldmatrix_x2(q1h0, q1h1, b1h + s * 32);
                ldmatrix_x2(q0l0, q0l1, b0l + s * 32);
                ldmatrix_x2(q1l0, q1l1, b1l + s * 32);
                mma4(hh0, ah[s], q0h0, q0h1);
                mma4(hh1, ah[s], q1h0, q1h1);
                mma4(hl0, ah[s], q0l0, q0l1);
                mma4(hl1, ah[s], q1l0, q1l1);
                mma4(lh0, al[s], q0h0, q0h1);
                mma4(lh1, al[s], q1h0, q1h1);
            }
            int code0 = chunk * CCHUNK + ntp * 16 + (lane & 3) * 2;
            int code1 = code0 + 8;
            float c;
            c = hh0[0] + hl0[0] + lh0[0]; ins4(c, code0,     vA, ixA);
            c = hh0[1] + hl0[1] + lh0[1]; ins4(c, code0 + 1, vA, ixA);
            c = hh0[2] + hl0[2] + lh0[2]; ins4(c, code0,     vB, ixB);
            c = hh0[3] + hl0[3] + lh0[3]; ins4(c, code0 + 1, vB, ixB);
            c = hh1[0] + hl1[0] + lh1[0]; ins4(c, code1,     vA, ixA);
            c = hh1[1] + hl1[1] + lh1[1]; ins4(c, code1 + 1, vA, ixA);
            c = hh1[2] + hl1[2] + lh1[2]; ins4(c, code1,     vB, ixB);
            c = hh1[3] + hl1[3] + lh1[3]; ins4(c, code1 + 1, vB, ixB);
        }
        __syncthreads();              // done reading buf before it is refilled
    }

    // ---- merge top-4 across the 4 lanes sharing each row ------------------
#pragma unroll
    for (int o = 1; o <= 2; o <<= 1) {
#pragma unroll
        for (int j = 0; j < 4; ++j) {
            float ovA = __shfl_xor_sync(0xffffffffu, vA[j], o);
            int   oiA = __shfl_xor_sync(0xffffffffu, ixA[j], o);
            float ovB = __shfl_xor_sync(0xffffffffu, vB[j], o);
            int   oiB = __shfl_xor_sync(0xffffffffu, ixB[j], o);
            ins4tb(ovA, oiA, vA, ixA);
            ins4tb(ovB, oiB, vB, ixB);
        }
    }
    if ((lane & 3) == 0) {
        int rA = w * 16 + (lane >> 2);
#pragma unroll
        for (int j = 0; j < 4; ++j) {
            sCand[rA][j]     = ixA[j];
            sCand[rA + 8][j] = ixB[j];
        }
    }
    __syncthreads();

    // ---- Phase 2: exact fp64 rescore, diff form (R2-validated) ------------
    {
        int r  = tid >> 1;
        int cA = sCand[r][(tid & 1) * 2];
        int cB = sCand[r][(tid & 1) * 2 + 1];
        const float4* x4 = reinterpret_cast<const float4*>(X + (size_t)(rowbase + r) * DDIM);
        const float4* ea = reinterpret_cast<const float4*>(E + (size_t)cA * DDIM);
        const float4* eb = reinterpret_cast<const float4*>(E + (size_t)cB * DDIM);
        double dA = 0.0, dB = 0.0;
#pragma unroll 4
        for (int j = 0; j < DDIM / 4; ++j) {
            float4 xv = x4[j], va = ea[j], vb = eb[j];
            double d;
            d = (double)xv.x - (double)va.x; dA += d * d;
            d = (double)xv.y - (double)va.y; dA += d * d;
            d = (double)xv.z - (double)va.z; dA += d * d;
            d = (double)xv.w - (double)va.w; dA += d * d;
            d = (double)xv.x - (double)vb.x; dB += d * d;
            d = (double)xv.y - (double)vb.y; dB += d * d;
            d = (double)xv.z - (double)vb.z; dB += d * d;
            d = (double)xv.w - (double)vb.w; dB += d * d;
        }
        double dmin = dA; int cmin = cA;
        if (dB < dmin || (dB == dmin && cB < cmin)) { dmin = dB; cmin = cB; }
        double od = __shfl_xor_sync(0xffffffffu, dmin, 1);
        int    oc = __shfl_xor_sync(0xffffffffu, cmin, 1);
        if (od < dmin || (od == dmin && oc < cmin)) { cmin = oc; }
        if ((tid & 1) == 0) sWin[r] = cmin;
    }
    __syncthreads();

    // ---- epilogue: gather + straight-through + loss (bit-exact to R2) -----
    float lsum = 0.0f;
    {
        const float4* xg = reinterpret_cast<const float4*>(X + (size_t)rowbase * DDIM);
        for (int i = tid; i < M_TILE * (DDIM / 4); i += THREADS) {
            int r = i >> 6, c4 = i & 63;
            int idx = sWin[r];
            float4 e = *reinterpret_cast<const float4*>(E + (size_t)idx * DDIM + c4 * 4);
            float4 x = xg[i];
            float4 d, q;
            d.x = e.x - x.x; d.y = e.y - x.y; d.z = e.z - x.z; d.w = e.w - x.w;
            q.x = x.x + d.x; q.y = x.y + d.y; q.z = x.z + d.z; q.w = x.w + d.w;
            lsum += d.x * d.x + d.y * d.y + d.z * d.z + d.w * d.w;
            *reinterpret_cast<float4*>(outQ + (size_t)(rowbase + r) * DDIM + c4 * 4) = q;
        }
    }
    if (tid < M_TILE) outIdx[rowbase + tid] = (float)sWin[tid];

#pragma unroll
    for (int s = 16; s >= 1; s >>= 1)
        lsum += __shfl_xor_sync(0xffffffffu, lsum, s);
    if (lane == 0) sRed[w] = lsum;
    __syncthreads();
    if (tid == 0) {
        float s = 0.0f;
#pragma unroll
        for (int i = 0; i < WARPS; ++i) s += sRed[i];
        atomicAdd(&g_loss_accum, (double)s);
    }
}

// ---------------------------------------------------------------------------
__global__ void vq_finalize(float* __restrict__ outLoss) {
    if (threadIdx.x == 0)
        *outLoss = (float)(g_loss_accum * (1.0 / (double)((size_t)NROWS * DDIM)));
}

// ---------------------------------------------------------------------------
extern "C" void kernel_launch(void* const* d_in, const int* in_sizes, int n_in,
                              void* d_out, int out_size) {
    (void)in_sizes; (void)n_in; (void)out_size;
    const float* X = (const float*)d_in[0];
    const float* E = (const float*)d_in[1];

    float* outQ    = (float*)d_out;
    float* outLoss = outQ + (size_t)NROWS * DDIM;   // 16777216
    float* outIdx  = outLoss + 1;                   // 16777217

    cudaFuncSetAttribute(vq_main_mma, cudaFuncAttributeMaxDynamicSharedMemorySize,
                         DYN_SMEM);

    vq_prep<<<KCODES / 8, 256>>>(E);
    vq_main_mma<<<NROWS / M_TILE, THREADS, DYN_SMEM>>>(X, E, outQ, outIdx);
    vq_finalize<<<1, 32>>>(outLoss);
}